// round 1
// baseline (speedup 1.0000x reference)
#include <cuda_runtime.h>
#include <math.h>

#define BB 64
#define TT 512
#define DD 512
#define TEMPV 0.07f
#define EPSV 1e-8f

// Scratch (device globals: no allocation allowed)
__device__ float g_anchor_a[BB * DD];
__device__ float g_anchor_v[BB * DD];
__device__ float g_neg_a[BB];
__device__ float g_neg_v[BB];
__device__ float g_pos[BB];
__device__ int   g_idx[BB];

// ---------------------------------------------------------------------------
// Kernel 1: one block per batch b.
//  - idx[b] = first index of max(mask[b,:])  (argmax-first semantics)
//  - normalized anchors a_anchor, v_anchor into global scratch
//  - pos[b] = dot(vn_anchor, an_anchor)/TEMP
//  - zero the negative accumulators
// ---------------------------------------------------------------------------
__global__ void k_anchor(const float* __restrict__ video,
                         const float* __restrict__ audio,
                         const int*   __restrict__ mask) {
    const int b   = blockIdx.x;
    const int tid = threadIdx.x;           // 256 threads

    __shared__ int   s_val[256];
    __shared__ int   s_ind[256];
    __shared__ float s_r0[256], s_r1[256], s_r2[256];

    // ---- argmax (first occurrence) over mask row ----
    int bestv = -2147483647, besti = 0;
    for (int t = tid; t < TT; t += 256) {
        int m = mask[b * TT + t];
        if (m > bestv) { bestv = m; besti = t; }   // ascending t -> keeps earliest
    }
    s_val[tid] = bestv; s_ind[tid] = besti;
    __syncthreads();
    for (int s = 128; s > 0; s >>= 1) {
        if (tid < s) {
            int vo = s_val[tid + s], io = s_ind[tid + s];
            if (vo > s_val[tid] || (vo == s_val[tid] && io < s_ind[tid])) {
                s_val[tid] = vo; s_ind[tid] = io;
            }
        }
        __syncthreads();
    }
    const int idx = s_ind[0];

    // ---- anchor norms + cross dot ----
    const float* arow = audio + ((size_t)b * TT + idx) * DD;
    const float* vrow = video + ((size_t)b * TT + idx) * DD;
    float sa = 0.f, sv = 0.f, sav = 0.f;
    for (int d = tid; d < DD; d += 256) {
        float a = arow[d], v = vrow[d];
        sa  += a * a;
        sv  += v * v;
        sav += a * v;
    }
    s_r0[tid] = sa; s_r1[tid] = sv; s_r2[tid] = sav;
    __syncthreads();
    for (int s = 128; s > 0; s >>= 1) {
        if (tid < s) {
            s_r0[tid] += s_r0[tid + s];
            s_r1[tid] += s_r1[tid + s];
            s_r2[tid] += s_r2[tid + s];
        }
        __syncthreads();
    }
    const float na = fmaxf(sqrtf(s_r0[0]), EPSV);
    const float nv = fmaxf(sqrtf(s_r1[0]), EPSV);

    const float inv_na = 1.0f / na;
    const float inv_nv = 1.0f / nv;
    for (int d = tid; d < DD; d += 256) {
        g_anchor_a[b * DD + d] = arow[d] * inv_na;
        g_anchor_v[b * DD + d] = vrow[d] * inv_nv;
    }
    if (tid == 0) {
        g_idx[b]   = idx;
        g_pos[b]   = s_r2[0] * inv_na * inv_nv * (1.0f / TEMPV);
        g_neg_a[b] = 0.f;
        g_neg_v[b] = 0.f;
    }
}

// ---------------------------------------------------------------------------
// Kernel 2: main bandwidth kernel. Grid = B * (T/ROWS) blocks, 256 threads.
// Each warp handles ROWS/8 t-rows of BOTH modalities:
//   sims_a2v[b,t] = dot(video_row, a_anchor) / (||video_row|| clamp) / TEMP
//   sims_v2a[b,t] = dot(audio_row, v_anchor) / (||audio_row|| clamp) / TEMP
// Accumulate exp(sim) for t != idx into g_neg_{a,v}[b].
// ---------------------------------------------------------------------------
#define ROWS 32   // t-rows per block (8 warps x 4 iterations)

__global__ void k_sims(const float* __restrict__ video,
                       const float* __restrict__ audio) {
    const int blk  = blockIdx.x;
    const int b    = blk / (TT / ROWS);
    const int t0   = (blk % (TT / ROWS)) * ROWS;
    const int tid  = threadIdx.x;
    const int warp = tid >> 5;
    const int lane = tid & 31;

    __shared__ __align__(16) float s_aa[DD];
    __shared__ __align__(16) float s_va[DD];
    __shared__ float s_neg[2];

    for (int d = tid; d < DD; d += 256) {
        s_aa[d] = g_anchor_a[b * DD + d];
        s_va[d] = g_anchor_v[b * DD + d];
    }
    if (tid < 2) s_neg[tid] = 0.f;
    __syncthreads();

    const int idx = g_idx[b];
    const float4* aa4 = reinterpret_cast<const float4*>(s_aa);
    const float4* va4 = reinterpret_cast<const float4*>(s_va);

    float acc_a = 0.f;   // contributes to neg_a (video rows vs audio anchor)
    float acc_v = 0.f;   // contributes to neg_v (audio rows vs video anchor)

    #pragma unroll
    for (int r = 0; r < ROWS / 8; ++r) {
        const int t = t0 + r * 8 + warp;
        const float4* vrow = reinterpret_cast<const float4*>(video + ((size_t)b * TT + t) * DD);
        const float4* arow = reinterpret_cast<const float4*>(audio + ((size_t)b * TT + t) * DD);

        float vd = 0.f, vn2 = 0.f, ad = 0.f, an2 = 0.f;
        #pragma unroll
        for (int i = 0; i < 4; ++i) {
            const int c = lane + i * 32;          // float4 index (d = 4c)
            float4 v  = vrow[c];
            float4 a  = arow[c];
            float4 pa = aa4[c];
            float4 pv = va4[c];
            vd  += v.x * pa.x + v.y * pa.y + v.z * pa.z + v.w * pa.w;
            vn2 += v.x * v.x  + v.y * v.y  + v.z * v.z  + v.w * v.w;
            ad  += a.x * pv.x + a.y * pv.y + a.z * pv.z + a.w * pv.w;
            an2 += a.x * a.x  + a.y * a.y  + a.z * a.z  + a.w * a.w;
        }
        #pragma unroll
        for (int s = 16; s > 0; s >>= 1) {
            vd  += __shfl_xor_sync(0xffffffffu, vd,  s);
            vn2 += __shfl_xor_sync(0xffffffffu, vn2, s);
            ad  += __shfl_xor_sync(0xffffffffu, ad,  s);
            an2 += __shfl_xor_sync(0xffffffffu, an2, s);
        }
        if (lane == 0 && t != idx) {
            float sim_a2v = vd / fmaxf(sqrtf(vn2), EPSV) * (1.0f / TEMPV);
            float sim_v2a = ad / fmaxf(sqrtf(an2), EPSV) * (1.0f / TEMPV);
            acc_a += expf(sim_a2v);
            acc_v += expf(sim_v2a);
        }
    }

    if (lane == 0) {
        atomicAdd(&s_neg[0], acc_a);
        atomicAdd(&s_neg[1], acc_v);
    }
    __syncthreads();
    if (tid == 0) atomicAdd(&g_neg_a[b], s_neg[0]);
    if (tid == 1) atomicAdd(&g_neg_v[b], s_neg[1]);
}

// ---------------------------------------------------------------------------
// Kernel 3: final scalar reduction.
// loss = sum_b [ 0.5*log(neg_a[b]) + 0.5*log(neg_v[b]) - pos[b] ] / B
// ---------------------------------------------------------------------------
__global__ void k_final(float* __restrict__ out) {
    const int tid = threadIdx.x;   // 64 threads
    __shared__ float s[64];
    float v = 0.5f * (logf(g_neg_a[tid]) + logf(g_neg_v[tid])) - g_pos[tid];
    s[tid] = v;
    __syncthreads();
    for (int st = 32; st > 0; st >>= 1) {
        if (tid < st) s[tid] += s[tid + st];
        __syncthreads();
    }
    if (tid == 0) out[0] = s[0] * (1.0f / BB);
}

extern "C" void kernel_launch(void* const* d_in, const int* in_sizes, int n_in,
                              void* d_out, int out_size) {
    const float* video = (const float*)d_in[0];
    const float* audio = (const float*)d_in[1];
    const int*   mask  = (const int*)d_in[2];
    float* out = (float*)d_out;

    k_anchor<<<BB, 256>>>(video, audio, mask);
    k_sims<<<BB * (TT / ROWS), 256>>>(video, audio);
    k_final<<<1, 64>>>(out);
}

// round 3
// speedup vs baseline: 1.1574x; 1.1574x over previous
#include <cuda_runtime.h>
#include <math.h>

#define BB 64
#define TT 512
#define DD 512
#define TEMPV 0.07f
#define EPSV 1e-8f
#define ROWS 32                       // t-rows per block (8 warps x 4 iters)
#define TILES (TT / ROWS)             // 16 tiles per batch
#define NBLK (BB * TILES)             // 1024 blocks
#define NWARP (NBLK * 8)              // 8192 warp-partials

// Scratch (device globals: no allocation allowed)
__device__ float g_pa[NWARP];         // per-warp partial exp-sums (a2v negatives)
__device__ float g_pv[NWARP];         // per-warp partial exp-sums (v2a negatives)
__device__ float g_pos[BB];

// ---------------------------------------------------------------------------
// Single fused bandwidth kernel. Grid = 1024 blocks x 256 threads.
// Every warp independently:
//   1. argmax-first of mask[b,:]          (2KB, L1/L2 broadcast across warps)
//   2. loads anchor rows into REGISTERS, computes norms via warp shuffle,
//      normalizes in registers           (4KB, L1/L2 broadcast)
//   3. processes 4 t-rows of both modalities: fused dot+norm+exp
// No __syncthreads anywhere. Partials written per-warp (no atomics, no init).
// ---------------------------------------------------------------------------
__global__ void __launch_bounds__(256) k_main(const float* __restrict__ video,
                                              const float* __restrict__ audio,
                                              const int*   __restrict__ mask) {
    const int blk  = blockIdx.x;
    const int b    = blk >> 4;            // blk / TILES
    const int t0   = (blk & 15) * ROWS;
    const int warp = threadIdx.x >> 5;
    const int lane = threadIdx.x & 31;

    // ---- 1. warp-local argmax (first occurrence) over mask row ----
    const int* __restrict__ mrow = mask + b * TT;
    int bestv = -2147483647, besti = TT;
    #pragma unroll
    for (int j = 0; j < TT / 32; ++j) {
        const int t = lane + j * 32;
        const int m = mrow[t];
        if (m > bestv || (m == bestv && t < besti)) { bestv = m; besti = t; }
    }
    #pragma unroll
    for (int s = 16; s > 0; s >>= 1) {
        int ov = __shfl_xor_sync(0xffffffffu, bestv, s);
        int oi = __shfl_xor_sync(0xffffffffu, besti, s);
        if (ov > bestv || (ov == bestv && oi < besti)) { bestv = ov; besti = oi; }
    }
    const int idx = besti;

    // ---- 2. anchors into registers, norms via warp shuffle ----
    const float4* __restrict__ arow4 =
        reinterpret_cast<const float4*>(audio + ((size_t)b * TT + idx) * DD);
    const float4* __restrict__ vrow4 =
        reinterpret_cast<const float4*>(video + ((size_t)b * TT + idx) * DD);

    float4 pa[4], pv[4];
    float sa = 0.f, sv = 0.f;
    #pragma unroll
    for (int i = 0; i < 4; ++i) {
        const int c = lane + i * 32;
        pa[i] = arow4[c];
        pv[i] = vrow4[c];
        sa += pa[i].x * pa[i].x + pa[i].y * pa[i].y + pa[i].z * pa[i].z + pa[i].w * pa[i].w;
        sv += pv[i].x * pv[i].x + pv[i].y * pv[i].y + pv[i].z * pv[i].z + pv[i].w * pv[i].w;
    }
    #pragma unroll
    for (int s = 16; s > 0; s >>= 1) {
        sa += __shfl_xor_sync(0xffffffffu, sa, s);
        sv += __shfl_xor_sync(0xffffffffu, sv, s);
    }
    const float inv_na = 1.0f / fmaxf(sqrtf(sa), EPSV);
    const float inv_nv = 1.0f / fmaxf(sqrtf(sv), EPSV);
    #pragma unroll
    for (int i = 0; i < 4; ++i) {
        pa[i].x *= inv_na; pa[i].y *= inv_na; pa[i].z *= inv_na; pa[i].w *= inv_na;
        pv[i].x *= inv_nv; pv[i].y *= inv_nv; pv[i].z *= inv_nv; pv[i].w *= inv_nv;
    }

    // ---- 3. main loop: 4 t-rows per warp ----
    float acc_a = 0.f;   // neg_a partial (video rows vs audio anchor)
    float acc_v = 0.f;   // neg_v partial (audio rows vs video anchor)

    #pragma unroll
    for (int r = 0; r < ROWS / 8; ++r) {
        const int t = t0 + r * 8 + warp;
        const float4* __restrict__ vr =
            reinterpret_cast<const float4*>(video + ((size_t)b * TT + t) * DD);
        const float4* __restrict__ ar =
            reinterpret_cast<const float4*>(audio + ((size_t)b * TT + t) * DD);

        float vd = 0.f, vn2 = 0.f, ad = 0.f, an2 = 0.f;
        #pragma unroll
        for (int i = 0; i < 4; ++i) {
            const int c = lane + i * 32;
            float4 v = vr[c];
            float4 a = ar[c];
            vd  += v.x * pa[i].x + v.y * pa[i].y + v.z * pa[i].z + v.w * pa[i].w;
            vn2 += v.x * v.x + v.y * v.y + v.z * v.z + v.w * v.w;
            ad  += a.x * pv[i].x + a.y * pv[i].y + a.z * pv[i].z + a.w * pv[i].w;
            an2 += a.x * a.x + a.y * a.y + a.z * a.z + a.w * a.w;
        }
        #pragma unroll
        for (int s = 16; s > 0; s >>= 1) {
            vd  += __shfl_xor_sync(0xffffffffu, vd,  s);
            vn2 += __shfl_xor_sync(0xffffffffu, vn2, s);
            ad  += __shfl_xor_sync(0xffffffffu, ad,  s);
            an2 += __shfl_xor_sync(0xffffffffu, an2, s);
        }
        if (lane == 0) {
            float sim_a2v = vd / fmaxf(sqrtf(vn2), EPSV) * (1.0f / TEMPV);
            float sim_v2a = ad / fmaxf(sqrtf(an2), EPSV) * (1.0f / TEMPV);
            if (t == idx) {
                g_pos[b] = sim_a2v;      // positive logit (exactly one warp hits this)
            } else {
                acc_a += expf(sim_a2v);
                acc_v += expf(sim_v2a);
            }
        }
    }

    if (lane == 0) {
        const int p = blk * 8 + warp;
        g_pa[p] = acc_a;
        g_pv[p] = acc_v;
    }
}

// ---------------------------------------------------------------------------
// Final reduction: 1 block x 1024 threads (32 warps, 2 batches per warp).
// loss = sum_b [ 0.5*(log(neg_a[b]) + log(neg_v[b])) - pos[b] ] / B
// ---------------------------------------------------------------------------
__global__ void k_final(float* __restrict__ out) {
    __shared__ float s_sum;
    if (threadIdx.x == 0) s_sum = 0.f;
    __syncthreads();

    const int warp = threadIdx.x >> 5;
    const int lane = threadIdx.x & 31;

    float local = 0.f;
    #pragma unroll
    for (int k = 0; k < 2; ++k) {
        const int b = warp * 2 + k;
        float na = 0.f, nv = 0.f;
        #pragma unroll
        for (int j = 0; j < 4; ++j) {
            const int p = b * 128 + lane + j * 32;   // 128 warp-partials per batch
            na += g_pa[p];
            nv += g_pv[p];
        }
        #pragma unroll
        for (int s = 16; s > 0; s >>= 1) {
            na += __shfl_xor_sync(0xffffffffu, na, s);
            nv += __shfl_xor_sync(0xffffffffu, nv, s);
        }
        if (lane == 0) local += 0.5f * (logf(na) + logf(nv)) - g_pos[b];
    }
    if (lane == 0) atomicAdd(&s_sum, local);
    __syncthreads();
    if (threadIdx.x == 0) out[0] = s_sum * (1.0f / BB);
}

extern "C" void kernel_launch(void* const* d_in, const int* in_sizes, int n_in,
                              void* d_out, int out_size) {
    const float* video = (const float*)d_in[0];
    const float* audio = (const float*)d_in[1];
    const int*   mask  = (const int*)d_in[2];
    float* out = (float*)d_out;

    k_main<<<NBLK, 256>>>(video, audio, mask);
    k_final<<<1, 1024>>>(out);
}

// round 4
// speedup vs baseline: 1.2330x; 1.0653x over previous
#include <cuda_runtime.h>
#include <math.h>

#define BB 64
#define TT 512
#define DD 512
#define TEMPV 0.07f
#define EPSV 1e-8f
#define ROWS 32                       // t-rows per block (8 warps x 4 iters)
#define TILES (TT / ROWS)             // 16 tiles per batch
#define NBLK (BB * TILES)             // 1024 blocks

// Scratch (device globals: no allocation allowed)
__device__ float g_blk_a[NBLK];       // per-block partial exp-sums (a2v negatives)
__device__ float g_blk_v[NBLK];       // per-block partial exp-sums (v2a negatives)
__device__ float g_pos[BB];
__device__ unsigned g_count = 0;      // ticket counter (self-resets each launch)

// ---------------------------------------------------------------------------
// Single fused kernel. Grid = 1024 blocks x 256 threads.
//  Phase A (per block, once): warp0 argmax-first of mask[b,:]; 256 threads
//    cooperatively stage both anchor rows into smem; each warp then builds
//    register-resident normalized anchors (warp-local norm via shuffle).
//  Phase B: each warp processes 4 t-rows of both modalities (fused
//    dot + row-norm + exp), block-reduces to 2 partials.
//  Phase C: last block (atomic ticket) reduces 1024+1024 partials -> loss.
// ---------------------------------------------------------------------------
__global__ void __launch_bounds__(256) k_main(const float* __restrict__ video,
                                              const float* __restrict__ audio,
                                              const int*   __restrict__ mask,
                                              float* __restrict__ out) {
    const int blk  = blockIdx.x;
    const int b    = blk >> 4;            // blk / TILES
    const int t0   = (blk & 15) * ROWS;
    const int tid  = threadIdx.x;
    const int warp = tid >> 5;
    const int lane = tid & 31;

    __shared__ __align__(16) float s_aa[DD];   // raw audio anchor row
    __shared__ __align__(16) float s_vv[DD];   // raw video anchor row
    __shared__ int   s_idx;
    __shared__ float s_par[16];                // 8 warps x {acc_a, acc_v}

    // ---- Phase A1: warp 0 does argmax-first over mask row ----
    if (warp == 0) {
        const int* __restrict__ mrow = mask + b * TT;
        int bestv = -2147483647, besti = TT;
        #pragma unroll
        for (int j = 0; j < TT / 32; ++j) {
            const int t = lane + j * 32;
            const int m = mrow[t];
            if (m > bestv || (m == bestv && t < besti)) { bestv = m; besti = t; }
        }
        #pragma unroll
        for (int s = 16; s > 0; s >>= 1) {
            int ov = __shfl_xor_sync(0xffffffffu, bestv, s);
            int oi = __shfl_xor_sync(0xffffffffu, besti, s);
            if (ov > bestv || (ov == bestv && oi < besti)) { bestv = ov; besti = oi; }
        }
        if (lane == 0) s_idx = besti;
    }
    __syncthreads();
    const int idx = s_idx;

    // ---- Phase A2: cooperative anchor stage (256 threads, 2 rows of 128 f4) ----
    {
        const float4* __restrict__ arow4 =
            reinterpret_cast<const float4*>(audio + ((size_t)b * TT + idx) * DD);
        const float4* __restrict__ vrow4 =
            reinterpret_cast<const float4*>(video + ((size_t)b * TT + idx) * DD);
        if (tid < 128) {
            reinterpret_cast<float4*>(s_aa)[tid] = arow4[tid];
        } else {
            reinterpret_cast<float4*>(s_vv)[tid - 128] = vrow4[tid - 128];
        }
    }
    __syncthreads();

    // ---- Phase A3: per-warp register anchors + warp-local norms ----
    float4 pa[4], pv[4];
    float sa = 0.f, sv = 0.f;
    #pragma unroll
    for (int i = 0; i < 4; ++i) {
        const int c = lane + i * 32;
        pa[i] = reinterpret_cast<const float4*>(s_aa)[c];
        pv[i] = reinterpret_cast<const float4*>(s_vv)[c];
        sa += pa[i].x * pa[i].x + pa[i].y * pa[i].y + pa[i].z * pa[i].z + pa[i].w * pa[i].w;
        sv += pv[i].x * pv[i].x + pv[i].y * pv[i].y + pv[i].z * pv[i].z + pv[i].w * pv[i].w;
    }
    #pragma unroll
    for (int s = 16; s > 0; s >>= 1) {
        sa += __shfl_xor_sync(0xffffffffu, sa, s);
        sv += __shfl_xor_sync(0xffffffffu, sv, s);
    }
    const float inv_na = 1.0f / fmaxf(sqrtf(sa), EPSV);
    const float inv_nv = 1.0f / fmaxf(sqrtf(sv), EPSV);
    #pragma unroll
    for (int i = 0; i < 4; ++i) {
        pa[i].x *= inv_na; pa[i].y *= inv_na; pa[i].z *= inv_na; pa[i].w *= inv_na;
        pv[i].x *= inv_nv; pv[i].y *= inv_nv; pv[i].z *= inv_nv; pv[i].w *= inv_nv;
    }

    // ---- Phase B: main loop, 4 t-rows per warp ----
    float acc_a = 0.f;   // neg_a partial (video rows vs audio anchor)
    float acc_v = 0.f;   // neg_v partial (audio rows vs video anchor)

    #pragma unroll
    for (int r = 0; r < ROWS / 8; ++r) {
        const int t = t0 + r * 8 + warp;
        const float4* __restrict__ vr =
            reinterpret_cast<const float4*>(video + ((size_t)b * TT + t) * DD);
        const float4* __restrict__ ar =
            reinterpret_cast<const float4*>(audio + ((size_t)b * TT + t) * DD);

        float vd = 0.f, vn2 = 0.f, ad = 0.f, an2 = 0.f;
        #pragma unroll
        for (int i = 0; i < 4; ++i) {
            const int c = lane + i * 32;
            float4 v = vr[c];
            float4 a = ar[c];
            vd  += v.x * pa[i].x + v.y * pa[i].y + v.z * pa[i].z + v.w * pa[i].w;
            vn2 += v.x * v.x + v.y * v.y + v.z * v.z + v.w * v.w;
            ad  += a.x * pv[i].x + a.y * pv[i].y + a.z * pv[i].z + a.w * pv[i].w;
            an2 += a.x * a.x + a.y * a.y + a.z * a.z + a.w * a.w;
        }
        #pragma unroll
        for (int s = 16; s > 0; s >>= 1) {
            vd  += __shfl_xor_sync(0xffffffffu, vd,  s);
            vn2 += __shfl_xor_sync(0xffffffffu, vn2, s);
            ad  += __shfl_xor_sync(0xffffffffu, ad,  s);
            an2 += __shfl_xor_sync(0xffffffffu, an2, s);
        }
        if (lane == 0) {
            float sim_a2v = vd / fmaxf(sqrtf(vn2), EPSV) * (1.0f / TEMPV);
            float sim_v2a = ad / fmaxf(sqrtf(an2), EPSV) * (1.0f / TEMPV);
            if (t == idx) {
                g_pos[b] = sim_a2v;      // exactly one warp chip-wide per b
            } else {
                acc_a += expf(sim_a2v);
                acc_v += expf(sim_v2a);
            }
        }
    }

    // ---- block-reduce 8 warp partials -> 2 values ----
    if (lane == 0) { s_par[warp] = acc_a; s_par[8 + warp] = acc_v; }
    __syncthreads();
    if (tid == 0) {
        float ba = 0.f, bv = 0.f;
        #pragma unroll
        for (int w = 0; w < 8; ++w) { ba += s_par[w]; bv += s_par[8 + w]; }
        g_blk_a[blk] = ba;
        g_blk_v[blk] = bv;
    }

    // ---- Phase C: last block finishes ----
    __shared__ bool s_last;
    if (tid == 0) {
        __threadfence();
        s_last = (atomicAdd(&g_count, 1u) == NBLK - 1);
    }
    __syncthreads();
    if (!s_last) return;

    __shared__ float s_red[64];
    if (tid < BB) {
        const int bb = tid;
        float na = 0.f, nv = 0.f;
        #pragma unroll
        for (int j = 0; j < TILES; ++j) {
            na += g_blk_a[bb * TILES + j];
            nv += g_blk_v[bb * TILES + j];
        }
        s_red[bb] = 0.5f * (logf(na) + logf(nv)) - g_pos[bb];
    }
    __syncthreads();
    if (tid < 32) {
        float v = s_red[tid] + s_red[tid + 32];
        #pragma unroll
        for (int s = 16; s > 0; s >>= 1)
            v += __shfl_xor_sync(0xffffffffu, v, s);
        if (tid == 0) {
            out[0] = v * (1.0f / BB);
            g_count = 0;                 // reset for next graph replay
        }
    }
}

extern "C" void kernel_launch(void* const* d_in, const int* in_sizes, int n_in,
                              void* d_out, int out_size) {
    const float* video = (const float*)d_in[0];
    const float* audio = (const float*)d_in[1];
    const int*   mask  = (const int*)d_in[2];
    float* out = (float*)d_out;

    k_main<<<NBLK, 256>>>(video, audio, mask, out);
}

// round 5
// speedup vs baseline: 1.4152x; 1.1478x over previous
#include <cuda_runtime.h>
#include <cuda_pipeline_primitives.h>
#include <math.h>

#define BB 64
#define TT 512
#define DD 512
#define TEMPV 0.07f
#define EPSV 1e-8f
#define JB 12                    // blocks per batch
#define NBLK (BB * JB)           // 768 blocks -> single wave at 6 blocks/SM
#define NW 4                     // warps per block (128 threads)

// Scratch (device globals: no allocation allowed)
__device__ float g_blk_a[NBLK];
__device__ float g_blk_v[NBLK];
__device__ float g_pos[BB];
__device__ unsigned g_count = 0;   // ticket; self-resets each launch

// ---------------------------------------------------------------------------
// Single fused kernel, 768 blocks x 128 threads. Block (b, j) handles rows
// t = j + 12k of batch b. Each warp owns a private 2-stage cp.async pipeline
// (video+audio row -> smem), so DRAM loads for row k+1 are in flight while
// row k is reduced. Lane i copies and later reads the same addresses ->
// no syncwarp/syncthreads in the mainloop.
// ---------------------------------------------------------------------------
__global__ void __launch_bounds__(128) k_main(const float* __restrict__ video,
                                              const float* __restrict__ audio,
                                              const int*   __restrict__ mask,
                                              float* __restrict__ out) {
    const int blk  = blockIdx.x;
    const int b    = blk / JB;
    const int j    = blk % JB;
    const int tid  = threadIdx.x;
    const int warp = tid >> 5;
    const int lane = tid & 31;

    __shared__ __align__(16) float4 s_pipe[NW][2][2][DD / 4]; // [warp][stage][v/a][128] = 32KB
    __shared__ __align__(16) float4 s_anc[2 * DD / 4];        // raw audio(0:128) + video(128:256) anchors
    __shared__ int   s_idx;
    __shared__ float s_par[2 * NW];

    // ---- prologue: warp 0 argmax-first over mask row ----
    if (warp == 0) {
        const int* __restrict__ mrow = mask + b * TT;
        int bestv = -2147483647, besti = TT;
        #pragma unroll
        for (int q = 0; q < TT / 32; ++q) {
            const int t = lane + q * 32;
            const int m = mrow[t];
            if (m > bestv || (m == bestv && t < besti)) { bestv = m; besti = t; }
        }
        #pragma unroll
        for (int s = 16; s > 0; s >>= 1) {
            int ov = __shfl_xor_sync(0xffffffffu, bestv, s);
            int oi = __shfl_xor_sync(0xffffffffu, besti, s);
            if (ov > bestv || (ov == bestv && oi < besti)) { bestv = ov; besti = oi; }
        }
        if (lane == 0) s_idx = besti;
    }
    __syncthreads();
    const int idx = s_idx;

    // ---- stage both anchor rows cooperatively (256 float4 / 128 threads) ----
    {
        const float4* __restrict__ arow4 =
            reinterpret_cast<const float4*>(audio + ((size_t)b * TT + idx) * DD);
        const float4* __restrict__ vrow4 =
            reinterpret_cast<const float4*>(video + ((size_t)b * TT + idx) * DD);
        s_anc[tid]       = arow4[tid];
        s_anc[128 + tid] = vrow4[tid];
    }
    __syncthreads();

    // ---- normalized anchors into registers (warp-local norm via shuffle) ----
    float4 pa[4], pv[4];
    float sa = 0.f, sv = 0.f;
    #pragma unroll
    for (int i = 0; i < 4; ++i) {
        const int c = lane + i * 32;
        pa[i] = s_anc[c];
        pv[i] = s_anc[128 + c];
        sa += pa[i].x * pa[i].x + pa[i].y * pa[i].y + pa[i].z * pa[i].z + pa[i].w * pa[i].w;
        sv += pv[i].x * pv[i].x + pv[i].y * pv[i].y + pv[i].z * pv[i].z + pv[i].w * pv[i].w;
    }
    #pragma unroll
    for (int s = 16; s > 0; s >>= 1) {
        sa += __shfl_xor_sync(0xffffffffu, sa, s);
        sv += __shfl_xor_sync(0xffffffffu, sv, s);
    }
    const float inv_na = 1.0f / fmaxf(sqrtf(sa), EPSV);
    const float inv_nv = 1.0f / fmaxf(sqrtf(sv), EPSV);
    #pragma unroll
    for (int i = 0; i < 4; ++i) {
        pa[i].x *= inv_na; pa[i].y *= inv_na; pa[i].z *= inv_na; pa[i].w *= inv_na;
        pv[i].x *= inv_nv; pv[i].y *= inv_nv; pv[i].z *= inv_nv; pv[i].w *= inv_nv;
    }

    // ---- mainloop: rows t = j + JB*k, warp w takes k = w, w+NW, ... ----
    const int kmax = (TT - 1 - j) / JB + 1;        // 42 or 43
    float acc_a = 0.f, acc_v = 0.f;

    // prime stage 0 with this warp's first row
    {
        const int t = j + JB * warp;
        const float4* __restrict__ vr =
            reinterpret_cast<const float4*>(video + ((size_t)b * TT + t) * DD);
        const float4* __restrict__ ar =
            reinterpret_cast<const float4*>(audio + ((size_t)b * TT + t) * DD);
        #pragma unroll
        for (int i = 0; i < 4; ++i) {
            const int c = lane + i * 32;
            __pipeline_memcpy_async(&s_pipe[warp][0][0][c], &vr[c], 16);
            __pipeline_memcpy_async(&s_pipe[warp][0][1][c], &ar[c], 16);
        }
        __pipeline_commit();
    }

    int stg = 0;
    for (int k = warp; k < kmax; k += NW) {
        const int knext = k + NW;
        if (knext < kmax) {
            const int tn = j + JB * knext;
            const float4* __restrict__ vr =
                reinterpret_cast<const float4*>(video + ((size_t)b * TT + tn) * DD);
            const float4* __restrict__ ar =
                reinterpret_cast<const float4*>(audio + ((size_t)b * TT + tn) * DD);
            #pragma unroll
            for (int i = 0; i < 4; ++i) {
                const int c = lane + i * 32;
                __pipeline_memcpy_async(&s_pipe[warp][stg ^ 1][0][c], &vr[c], 16);
                __pipeline_memcpy_async(&s_pipe[warp][stg ^ 1][1][c], &ar[c], 16);
            }
            __pipeline_commit();
            __pipeline_wait_prior(1);
        } else {
            __pipeline_wait_prior(0);
        }

        // compute on stage stg (each lane reads only bytes it copied)
        float vd = 0.f, vn2 = 0.f, ad = 0.f, an2 = 0.f;
        #pragma unroll
        for (int i = 0; i < 4; ++i) {
            const int c = lane + i * 32;
            float4 v = s_pipe[warp][stg][0][c];
            float4 a = s_pipe[warp][stg][1][c];
            vd  += v.x * pa[i].x + v.y * pa[i].y + v.z * pa[i].z + v.w * pa[i].w;
            vn2 += v.x * v.x + v.y * v.y + v.z * v.z + v.w * v.w;
            ad  += a.x * pv[i].x + a.y * pv[i].y + a.z * pv[i].z + a.w * pv[i].w;
            an2 += a.x * a.x + a.y * a.y + a.z * a.z + a.w * a.w;
        }
        #pragma unroll
        for (int s = 16; s > 0; s >>= 1) {
            vd  += __shfl_xor_sync(0xffffffffu, vd,  s);
            vn2 += __shfl_xor_sync(0xffffffffu, vn2, s);
            ad  += __shfl_xor_sync(0xffffffffu, ad,  s);
            an2 += __shfl_xor_sync(0xffffffffu, an2, s);
        }
        if (lane == 0) {
            const int t = j + JB * k;
            float sim_a2v = vd / fmaxf(sqrtf(vn2), EPSV) * (1.0f / TEMPV);
            float sim_v2a = ad / fmaxf(sqrtf(an2), EPSV) * (1.0f / TEMPV);
            if (t == idx) {
                g_pos[b] = sim_a2v;      // exactly one warp chip-wide per b
            } else {
                acc_a += __expf(sim_a2v);
                acc_v += __expf(sim_v2a);
            }
        }
        stg ^= 1;
    }

    // ---- block-reduce 4 warp partials ----
    if (lane == 0) { s_par[warp] = acc_a; s_par[NW + warp] = acc_v; }
    __syncthreads();
    if (tid == 0) {
        float ba = 0.f, bv = 0.f;
        #pragma unroll
        for (int w = 0; w < NW; ++w) { ba += s_par[w]; bv += s_par[NW + w]; }
        g_blk_a[blk] = ba;
        g_blk_v[blk] = bv;
    }

    // ---- last block finishes ----
    __shared__ bool s_last;
    if (tid == 0) {
        __threadfence();
        s_last = (atomicAdd(&g_count, 1u) == NBLK - 1);
    }
    __syncthreads();
    if (!s_last) return;

    __shared__ float s_red[BB];
    if (tid < BB) {
        float na = 0.f, nv = 0.f;
        #pragma unroll
        for (int q = 0; q < JB; ++q) {
            na += g_blk_a[tid * JB + q];
            nv += g_blk_v[tid * JB + q];
        }
        s_red[tid] = 0.5f * (__logf(na) + __logf(nv)) - g_pos[tid];
    }
    __syncthreads();
    if (tid < 32) {
        float v = s_red[tid] + s_red[tid + 32];
        #pragma unroll
        for (int s = 16; s > 0; s >>= 1)
            v += __shfl_xor_sync(0xffffffffu, v, s);
        if (tid == 0) {
            out[0] = v * (1.0f / BB);
            g_count = 0;                 // reset for next graph replay
        }
    }
}

extern "C" void kernel_launch(void* const* d_in, const int* in_sizes, int n_in,
                              void* d_out, int out_size) {
    const float* video = (const float*)d_in[0];
    const float* audio = (const float*)d_in[1];
    const int*   mask  = (const int*)d_in[2];
    float* out = (float*)d_out;

    k_main<<<NBLK, 128>>>(video, audio, mask, out);
}

// round 7
// speedup vs baseline: 1.5028x; 1.0619x over previous
#include <cuda_runtime.h>
#include <cuda_pipeline_primitives.h>
#include <math.h>

#define BB 64
#define TT 512
#define DD 512
#define TEMPV 0.07f
#define EPSV 1e-8f
#define JB 9                     // blocks per batch
#define NBLK (BB * JB)           // 576 blocks  (<= 148 SMs * 4 blocks = 592 -> 1 wave)
#define NW 4                     // warps per block (128 threads)
#define NSTG 3                   // cp.async pipeline stages per warp

// Scratch (device globals: no allocation allowed)
__device__ float g_blk_a[NBLK];
__device__ float g_blk_v[NBLK];
__device__ float g_pos[BB];
__device__ unsigned g_count = 0;   // ticket; self-resets each launch

struct SmemLayout {
    float4 pipe[NW][NSTG][2][DD / 4];   // 48 KB: [warp][stage][v/a][128]
    float4 anc[2 * DD / 4];             // 4 KB: audio(0:128) + video(128:256) raw anchors
    int    idx;
    float  par[2 * NW];
    int    last;
};

// ---------------------------------------------------------------------------
// Single fused kernel, 576 blocks x 128 threads. Block (b, j) handles rows
// t = j + 9k. Each warp runs a private 3-stage cp.async ring: while computing
// row i, rows i+1 and i+2 are in flight (8 KB outstanding per warp).
// Lane x copies and later reads the same addresses -> no mainloop barriers.
// ---------------------------------------------------------------------------
__global__ void __launch_bounds__(128) k_main(const float* __restrict__ video,
                                              const float* __restrict__ audio,
                                              const int*   __restrict__ mask,
                                              float* __restrict__ out) {
    extern __shared__ __align__(16) char smem_raw[];
    SmemLayout& sm = *reinterpret_cast<SmemLayout*>(smem_raw);

    const int blk  = blockIdx.x;
    const int b    = blk / JB;
    const int j    = blk % JB;
    const int tid  = threadIdx.x;
    const int warp = tid >> 5;
    const int lane = tid & 31;

    // ---- prologue: warp 0 argmax-first over mask row ----
    if (warp == 0) {
        const int* __restrict__ mrow = mask + b * TT;
        int bestv = -2147483647, besti = TT;
        #pragma unroll
        for (int q = 0; q < TT / 32; ++q) {
            const int t = lane + q * 32;
            const int m = mrow[t];
            if (m > bestv || (m == bestv && t < besti)) { bestv = m; besti = t; }
        }
        #pragma unroll
        for (int s = 16; s > 0; s >>= 1) {
            int ov = __shfl_xor_sync(0xffffffffu, bestv, s);
            int oi = __shfl_xor_sync(0xffffffffu, besti, s);
            if (ov > bestv || (ov == bestv && oi < besti)) { bestv = ov; besti = oi; }
        }
        if (lane == 0) sm.idx = besti;
    }
    __syncthreads();
    const int idx = sm.idx;

    // ---- stage both anchor rows cooperatively ----
    {
        const float4* __restrict__ arow4 =
            reinterpret_cast<const float4*>(audio + ((size_t)b * TT + idx) * DD);
        const float4* __restrict__ vrow4 =
            reinterpret_cast<const float4*>(video + ((size_t)b * TT + idx) * DD);
        sm.anc[tid]       = arow4[tid];
        sm.anc[128 + tid] = vrow4[tid];
    }
    __syncthreads();

    // ---- normalized anchors into registers (warp-local norm via shuffle) ----
    float4 pa[4], pv[4];
    float sa = 0.f, sv = 0.f;
    #pragma unroll
    for (int i = 0; i < 4; ++i) {
        const int c = lane + i * 32;
        pa[i] = sm.anc[c];
        pv[i] = sm.anc[128 + c];
        sa += pa[i].x * pa[i].x + pa[i].y * pa[i].y + pa[i].z * pa[i].z + pa[i].w * pa[i].w;
        sv += pv[i].x * pv[i].x + pv[i].y * pv[i].y + pv[i].z * pv[i].z + pv[i].w * pv[i].w;
    }
    #pragma unroll
    for (int s = 16; s > 0; s >>= 1) {
        sa += __shfl_xor_sync(0xffffffffu, sa, s);
        sv += __shfl_xor_sync(0xffffffffu, sv, s);
    }
    const float inv_na = 1.0f / fmaxf(sqrtf(sa), EPSV);
    const float inv_nv = 1.0f / fmaxf(sqrtf(sv), EPSV);
    #pragma unroll
    for (int i = 0; i < 4; ++i) {
        pa[i].x *= inv_na; pa[i].y *= inv_na; pa[i].z *= inv_na; pa[i].w *= inv_na;
        pv[i].x *= inv_nv; pv[i].y *= inv_nv; pv[i].z *= inv_nv; pv[i].w *= inv_nv;
    }

    // ---- mainloop: this block owns t = j + JB*k; warp takes k = warp + NW*i ----
    const int kmax  = (TT - 1 - j) / JB + 1;                       // 56 or 57
    const int niter = (warp < kmax) ? ((kmax - 1 - warp) / NW + 1) : 0;

    float acc_a = 0.f, acc_v = 0.f;

    // prime stages 0..NSTG-2 (one commit group each, possibly empty)
    #pragma unroll
    for (int p = 0; p < NSTG - 1; ++p) {
        if (p < niter) {
            const int t = j + JB * (warp + NW * p);
            const float4* __restrict__ vr =
                reinterpret_cast<const float4*>(video + ((size_t)b * TT + t) * DD);
            const float4* __restrict__ ar =
                reinterpret_cast<const float4*>(audio + ((size_t)b * TT + t) * DD);
            #pragma unroll
            for (int i = 0; i < 4; ++i) {
                const int c = lane + i * 32;
                __pipeline_memcpy_async(&sm.pipe[warp][p][0][c], &vr[c], 16);
                __pipeline_memcpy_async(&sm.pipe[warp][p][1][c], &ar[c], 16);
            }
        }
        __pipeline_commit();
    }

    for (int it = 0; it < niter; ++it) {
        const int stg = it % NSTG;
        __pipeline_wait_prior(NSTG - 2);     // row `it` landed

        // compute on stage stg
        float vd = 0.f, vn2 = 0.f, ad = 0.f, an2 = 0.f;
        #pragma unroll
        for (int i = 0; i < 4; ++i) {
            const int c = lane + i * 32;
            float4 v = sm.pipe[warp][stg][0][c];
            float4 a = sm.pipe[warp][stg][1][c];
            vd  += v.x * pa[i].x + v.y * pa[i].y + v.z * pa[i].z + v.w * pa[i].w;
            vn2 += v.x * v.x + v.y * v.y + v.z * v.z + v.w * v.w;
            ad  += a.x * pv[i].x + a.y * pv[i].y + a.z * pv[i].z + a.w * pv[i].w;
            an2 += a.x * a.x + a.y * a.y + a.z * a.z + a.w * a.w;
        }
        #pragma unroll
        for (int s = 16; s > 0; s >>= 1) {
            vd  += __shfl_xor_sync(0xffffffffu, vd,  s);
            vn2 += __shfl_xor_sync(0xffffffffu, vn2, s);
            ad  += __shfl_xor_sync(0xffffffffu, ad,  s);
            an2 += __shfl_xor_sync(0xffffffffu, an2, s);
        }
        if (lane == 0) {
            const int t = j + JB * (warp + NW * it);
            float sim_a2v = vd / fmaxf(sqrtf(vn2), EPSV) * (1.0f / TEMPV);
            float sim_v2a = ad / fmaxf(sqrtf(an2), EPSV) * (1.0f / TEMPV);
            if (t == idx) {
                g_pos[b] = sim_a2v;          // exactly one warp chip-wide per b
            } else {
                acc_a += __expf(sim_a2v);
                acc_v += __expf(sim_v2a);
            }
        }

        // issue row it+NSTG-1 into the stage we just freed... (ring: (it+NSTG-1)%NSTG)
        const int kn = it + NSTG - 1;
        if (kn < niter) {
            const int sn = kn % NSTG;
            const int tn = j + JB * (warp + NW * kn);
            const float4* __restrict__ vr =
                reinterpret_cast<const float4*>(video + ((size_t)b * TT + tn) * DD);
            const float4* __restrict__ ar =
                reinterpret_cast<const float4*>(audio + ((size_t)b * TT + tn) * DD);
            #pragma unroll
            for (int i = 0; i < 4; ++i) {
                const int c = lane + i * 32;
                __pipeline_memcpy_async(&sm.pipe[warp][sn][0][c], &vr[c], 16);
                __pipeline_memcpy_async(&sm.pipe[warp][sn][1][c], &ar[c], 16);
            }
        }
        __pipeline_commit();
    }

    // ---- block-reduce 4 warp partials ----
    if (lane == 0) { sm.par[warp] = acc_a; sm.par[NW + warp] = acc_v; }
    __syncthreads();
    if (tid == 0) {
        float ba = 0.f, bv = 0.f;
        #pragma unroll
        for (int w = 0; w < NW; ++w) { ba += sm.par[w]; bv += sm.par[NW + w]; }
        g_blk_a[blk] = ba;
        g_blk_v[blk] = bv;
    }

    // ---- last block finishes ----
    if (tid == 0) {
        __threadfence();
        sm.last = (atomicAdd(&g_count, 1u) == NBLK - 1) ? 1 : 0;
    }
    __syncthreads();
    if (!sm.last) return;

    __shared__ float s_red[BB];
    if (tid < BB) {
        float na = 0.f, nv = 0.f;
        #pragma unroll
        for (int q = 0; q < JB; ++q) {
            na += g_blk_a[tid * JB + q];
            nv += g_blk_v[tid * JB + q];
        }
        s_red[tid] = 0.5f * (__logf(na) + __logf(nv)) - g_pos[tid];
    }
    __syncthreads();
    if (tid < 32) {
        float v = s_red[tid] + s_red[tid + 32];
        #pragma unroll
        for (int s = 16; s > 0; s >>= 1)
            v += __shfl_xor_sync(0xffffffffu, v, s);
        if (tid == 0) {
            out[0] = v * (1.0f / BB);
            g_count = 0;                 // reset for next graph replay
        }
    }
}

extern "C" void kernel_launch(void* const* d_in, const int* in_sizes, int n_in,
                              void* d_out, int out_size) {
    const float* video = (const float*)d_in[0];
    const float* audio = (const float*)d_in[1];
    const int*   mask  = (const int*)d_in[2];
    float* out = (float*)d_out;

    static int smem_set = 0;
    const int smem_bytes = (int)sizeof(SmemLayout);
    if (!smem_set) {
        cudaFuncSetAttribute(k_main, cudaFuncAttributeMaxDynamicSharedMemorySize, smem_bytes);
        smem_set = 1;
    }
    k_main<<<NBLK, 128, smem_bytes>>>(video, audio, mask, out);
}

// round 10
// speedup vs baseline: 1.5145x; 1.0078x over previous
#include <cuda_runtime.h>
#include <cuda_pipeline_primitives.h>
#include <math.h>

#define BB 64
#define TT 512
#define DD 512
#define TEMPV 0.07f
#define EPSV 1e-8f
#define JB 9                     // blocks per batch
#define NBLK (BB * JB)           // 576 blocks  (<= 148 SMs * 4 blocks -> 1 wave)
#define NW 4                     // warps per block (128 threads)
#define NSTG 3                   // cp.async pipeline stages per warp

// Scratch (device globals: no allocation allowed)
__device__ float g_blk_a[NBLK];
__device__ float g_blk_v[NBLK];
__device__ float g_pos[BB];
__device__ unsigned g_count = 0;   // ticket; self-resets each launch

struct SmemLayout {
    float4 pipe[NW][NSTG][2][DD / 4];   // 48 KB: [warp][stage][v/a][128]
    float4 anc[2 * DD / 4];             // 4 KB: audio(0:128) + video(128:256) raw anchors
    int    idx;
    float  par[2 * NW];
    int    last;
};

// ---------------------------------------------------------------------------
// Single fused kernel, 576 blocks x 128 threads. Block (b, j) handles rows
// t = j + 9k. Each warp runs a private 3-stage cp.async ring with
// ISSUE-BEFORE-COMPUTE ordering: while computing row i, rows i+1 AND i+2 are
// in flight (8 KB outstanding per warp). Mainloop priming loads are issued
// before the argmax/anchor prologue so DRAM is busy from cycle ~0.
// Lane x copies and later reads the same addresses -> no mainloop barriers.
// ---------------------------------------------------------------------------
__global__ void __launch_bounds__(128) k_main(const float* __restrict__ video,
                                              const float* __restrict__ audio,
                                              const int*   __restrict__ mask,
                                              float* __restrict__ out) {
    extern __shared__ __align__(16) char smem_raw[];
    SmemLayout& sm = *reinterpret_cast<SmemLayout*>(smem_raw);

    const int blk  = blockIdx.x;
    const int b    = blk / JB;
    const int j    = blk % JB;
    const int tid  = threadIdx.x;
    const int warp = tid >> 5;
    const int lane = tid & 31;

    const int kmax  = (TT - 1 - j) / JB + 1;
    const int niter = (warp < kmax) ? ((kmax - 1 - warp) / NW + 1) : 0;

    // ---- FIRST: prime pipeline stages 0..NSTG-2 (independent of idx) ----
    #pragma unroll
    for (int p = 0; p < NSTG - 1; ++p) {
        if (p < niter) {
            const int t = j + JB * (warp + NW * p);
            const float4* __restrict__ vr =
                reinterpret_cast<const float4*>(video + ((size_t)b * TT + t) * DD);
            const float4* __restrict__ ar =
                reinterpret_cast<const float4*>(audio + ((size_t)b * TT + t) * DD);
            #pragma unroll
            for (int i = 0; i < 4; ++i) {
                const int c = lane + i * 32;
                __pipeline_memcpy_async(&sm.pipe[warp][p][0][c], &vr[c], 16);
                __pipeline_memcpy_async(&sm.pipe[warp][p][1][c], &ar[c], 16);
            }
        }
        __pipeline_commit();
    }

    // ---- prologue: warp 0 argmax-first over mask row (overlaps priming) ----
    if (warp == 0) {
        const int* __restrict__ mrow = mask + b * TT;
        int bestv = -2147483647, besti = TT;
        #pragma unroll
        for (int q = 0; q < TT / 32; ++q) {
            const int t = lane + q * 32;
            const int m = mrow[t];
            if (m > bestv || (m == bestv && t < besti)) { bestv = m; besti = t; }
        }
        #pragma unroll
        for (int s = 16; s > 0; s >>= 1) {
            int ov = __shfl_xor_sync(0xffffffffu, bestv, s);
            int oi = __shfl_xor_sync(0xffffffffu, besti, s);
            if (ov > bestv || (ov == bestv && oi < besti)) { bestv = ov; besti = oi; }
        }
        if (lane == 0) sm.idx = besti;
    }
    __syncthreads();
    const int idx = sm.idx;

    // ---- stage both anchor rows cooperatively ----
    {
        const float4* __restrict__ arow4 =
            reinterpret_cast<const float4*>(audio + ((size_t)b * TT + idx) * DD);
        const float4* __restrict__ vrow4 =
            reinterpret_cast<const float4*>(video + ((size_t)b * TT + idx) * DD);
        sm.anc[tid]       = arow4[tid];
        sm.anc[128 + tid] = vrow4[tid];
    }
    __syncthreads();

    // ---- normalized anchors into registers (warp-local norm via shuffle) ----
    float4 pa[4], pv[4];
    float sa = 0.f, sv = 0.f;
    #pragma unroll
    for (int i = 0; i < 4; ++i) {
        const int c = lane + i * 32;
        pa[i] = sm.anc[c];
        pv[i] = sm.anc[128 + c];
        sa += pa[i].x * pa[i].x + pa[i].y * pa[i].y + pa[i].z * pa[i].z + pa[i].w * pa[i].w;
        sv += pv[i].x * pv[i].x + pv[i].y * pv[i].y + pv[i].z * pv[i].z + pv[i].w * pv[i].w;
    }
    #pragma unroll
    for (int s = 16; s > 0; s >>= 1) {
        sa += __shfl_xor_sync(0xffffffffu, sa, s);
        sv += __shfl_xor_sync(0xffffffffu, sv, s);
    }
    const float inv_na = 1.0f / fmaxf(sqrtf(sa), EPSV);
    const float inv_nv = 1.0f / fmaxf(sqrtf(sv), EPSV);
    #pragma unroll
    for (int i = 0; i < 4; ++i) {
        pa[i].x *= inv_na; pa[i].y *= inv_na; pa[i].z *= inv_na; pa[i].w *= inv_na;
        pv[i].x *= inv_nv; pv[i].y *= inv_nv; pv[i].z *= inv_nv; pv[i].w *= inv_nv;
    }

    float acc_a = 0.f, acc_v = 0.f;

    for (int it = 0; it < niter; ++it) {
        const int stg = it % NSTG;
        __pipeline_wait_prior(NSTG - 2);     // row `it` landed

        // ISSUE FIRST: row it+NSTG-1 into stage (it-1)%NSTG (consumed last iter)
        const int kn = it + NSTG - 1;
        if (kn < niter) {
            const int sn = kn % NSTG;
            const int tn = j + JB * (warp + NW * kn);
            const float4* __restrict__ vr =
                reinterpret_cast<const float4*>(video + ((size_t)b * TT + tn) * DD);
            const float4* __restrict__ ar =
                reinterpret_cast<const float4*>(audio + ((size_t)b * TT + tn) * DD);
            #pragma unroll
            for (int i = 0; i < 4; ++i) {
                const int c = lane + i * 32;
                __pipeline_memcpy_async(&sm.pipe[warp][sn][0][c], &vr[c], 16);
                __pipeline_memcpy_async(&sm.pipe[warp][sn][1][c], &ar[c], 16);
            }
        }
        __pipeline_commit();

        // compute on stage stg (rows it+1, it+2 now both in flight)
        float vd = 0.f, vn2 = 0.f, ad = 0.f, an2 = 0.f;
        #pragma unroll
        for (int i = 0; i < 4; ++i) {
            const int c = lane + i * 32;
            float4 v = sm.pipe[warp][stg][0][c];
            float4 a = sm.pipe[warp][stg][1][c];
            vd  += v.x * pa[i].x + v.y * pa[i].y + v.z * pa[i].z + v.w * pa[i].w;
            vn2 += v.x * v.x + v.y * v.y + v.z * v.z + v.w * v.w;
            ad  += a.x * pv[i].x + a.y * pv[i].y + a.z * pv[i].z + a.w * pv[i].w;
            an2 += a.x * a.x + a.y * a.y + a.z * a.z + a.w * a.w;
        }
        #pragma unroll
        for (int s = 16; s > 0; s >>= 1) {
            vd  += __shfl_xor_sync(0xffffffffu, vd,  s);
            vn2 += __shfl_xor_sync(0xffffffffu, vn2, s);
            ad  += __shfl_xor_sync(0xffffffffu, ad,  s);
            an2 += __shfl_xor_sync(0xffffffffu, an2, s);
        }
        if (lane == 0) {
            const int t = j + JB * (warp + NW * it);
            float sim_a2v = vd / fmaxf(sqrtf(vn2), EPSV) * (1.0f / TEMPV);
            float sim_v2a = ad / fmaxf(sqrtf(an2), EPSV) * (1.0f / TEMPV);
            if (t == idx) {
                g_pos[b] = sim_a2v;          // exactly one warp chip-wide per b
            } else {
                acc_a += __expf(sim_a2v);
                acc_v += __expf(sim_v2a);
            }
        }
    }

    // ---- block-reduce 4 warp partials ----
    if (lane == 0) { sm.par[warp] = acc_a; sm.par[NW + warp] = acc_v; }
    __syncthreads();
    if (tid == 0) {
        float ba = 0.f, bv = 0.f;
        #pragma unroll
        for (int w = 0; w < NW; ++w) { ba += sm.par[w]; bv += sm.par[NW + w]; }
        g_blk_a[blk] = ba;
        g_blk_v[blk] = bv;
    }

    // ---- last block finishes ----
    if (tid == 0) {
        __threadfence();
        sm.last = (atomicAdd(&g_count, 1u) == NBLK - 1) ? 1 : 0;
    }
    __syncthreads();
    if (!sm.last) return;

    __shared__ float s_red[BB];
    if (tid < BB) {
        float na = 0.f, nv = 0.f;
        #pragma unroll
        for (int q = 0; q < JB; ++q) {
            na += g_blk_a[tid * JB + q];
            nv += g_blk_v[tid * JB + q];
        }
        s_red[tid] = 0.5f * (__logf(na) + __logf(nv)) - g_pos[tid];
    }
    __syncthreads();
    if (tid < 32) {
        float v = s_red[tid] + s_red[tid + 32];
        #pragma unroll
        for (int s = 16; s > 0; s >>= 1)
            v += __shfl_xor_sync(0xffffffffu, v, s);
        if (tid == 0) {
            out[0] = v * (1.0f / BB);
            g_count = 0;                 // reset for next graph replay
        }
    }
}

extern "C" void kernel_launch(void* const* d_in, const int* in_sizes, int n_in,
                              void* d_out, int out_size) {
    const float* video = (const float*)d_in[0];
    const float* audio = (const float*)d_in[1];
    const int*   mask  = (const int*)d_in[2];
    float* out = (float*)d_out;

    static int smem_set = 0;
    const int smem_bytes = (int)sizeof(SmemLayout);
    if (!smem_set) {
        cudaFuncSetAttribute(k_main, cudaFuncAttributeMaxDynamicSharedMemorySize, smem_bytes);
        smem_set = 1;
    }
    k_main<<<NBLK, 128, smem_bytes>>>(video, audio, mask, out);
}